// round 16
// baseline (speedup 1.0000x reference)
#include <cuda_runtime.h>
#include <cuda_fp16.h>
#include <cstdint>

// ---------------- problem constants ----------------
#define B_    8
#define K_    128
#define S_    256
#define NOUT  16384
#define M_    2048
#define BM    128
#define BN    128
#define BK    32
#define NKB   4
#define STAGE_BYTES (BK * 256 * 2)             // A[32][256B] + B[32][256B] = 16KB
#define SM_TOTAL (NKB * STAGE_BYTES)           // 64KB, full-K prefetch

// ---------------- scratch: fp16, SAME layout as sources ----------------
__device__ __align__(16) __half g_A[B_ * K_ * S_];     // [n][k][s]   512 KB
__device__ __align__(16) __half g_B[K_ * NOUT];        // [k][j]      4 MB

// ---------------- helpers ----------------
__device__ __forceinline__ uint32_t smem_u32(const void* p) {
    uint32_t a;
    asm("{ .reg .u64 t; cvta.to.shared.u64 t, %1; cvt.u32.u64 %0, t; }" : "=r"(a) : "l"(p));
    return a;
}
__device__ __forceinline__ void cp_async16(uint32_t saddr, const void* gaddr) {
    asm volatile("cp.async.cg.shared.global [%0], [%1], 16;" :: "r"(saddr), "l"(gaddr));
}
__device__ __forceinline__ void cp_commit() {
    asm volatile("cp.async.commit_group;" ::: "memory");
}
template <int N>
__device__ __forceinline__ void cp_wait() {
    asm volatile("cp.async.wait_group %0;" :: "n"(N) : "memory");
}
__device__ __forceinline__ void ldsm4t(uint32_t& r0, uint32_t& r1, uint32_t& r2, uint32_t& r3,
                                       uint32_t addr) {
    asm volatile("ldmatrix.sync.aligned.m8n8.x4.trans.shared.b16 {%0,%1,%2,%3}, [%4];"
                 : "=r"(r0), "=r"(r1), "=r"(r2), "=r"(r3) : "r"(addr));
}
__device__ __forceinline__ void mma16816(float* d, uint32_t a0, uint32_t a1, uint32_t a2,
                                         uint32_t a3, uint32_t b0, uint32_t b1) {
    asm volatile(
        "mma.sync.aligned.m16n8k16.row.col.f32.f16.f16.f32 "
        "{%0,%1,%2,%3}, {%4,%5,%6,%7}, {%8,%9}, {%0,%1,%2,%3};"
        : "+f"(d[0]), "+f"(d[1]), "+f"(d[2]), "+f"(d[3])
        : "r"(a0), "r"(a1), "r"(a2), "r"(a3), "r"(b0), "r"(b1));
}

// ---------------- pre-kernel: pure streaming fp32 -> fp16 cast ----------------
__global__ __launch_bounds__(256)
void convert_kernel(const float* __restrict__ y, const float* __restrict__ W) {
    const int bid = blockIdx.x;
    const float* s;
    __half* d;
    if (bid < 1024) {
        size_t u = (size_t)bid * 256 + threadIdx.x;
        s = W + u * 8;  d = g_B + u * 8;
    } else {
        size_t u = (size_t)(bid - 1024) * 256 + threadIdx.x;
        s = y + u * 8;  d = g_A + u * 8;
    }
    float4 v0 = ((const float4*)s)[0];
    float4 v1 = ((const float4*)s)[1];
    __half2 h0 = __floats2half2_rn(v0.x, v0.y);
    __half2 h1 = __floats2half2_rn(v0.z, v0.w);
    __half2 h2 = __floats2half2_rn(v1.x, v1.y);
    __half2 h3 = __floats2half2_rn(v1.z, v1.w);
    uint4 o;
    o.x = *(uint32_t*)&h0; o.y = *(uint32_t*)&h1;
    o.z = *(uint32_t*)&h2; o.w = *(uint32_t*)&h3;
    *(uint4*)d = o;
    cudaTriggerProgrammaticLaunchCompletion();
}

// smem tile layout: [32 k-rows][256B], 16B chunk swizzle  c' = c ^ (k & 7)
#define TSWZ(k, c) ((c) ^ ((k) & 7))

// ---------------- main GEMM kernel: hoisted-fragment compute + PDL ----------------
__global__ __launch_bounds__(256, 2)
void gemm_fp16_kernel(float* __restrict__ out) {
    extern __shared__ char smem[];
    const uint32_t sbase = smem_u32(smem);
    const int tid  = threadIdx.x;
    const int lane = tid & 31;
    const int w    = tid >> 5;
    const int wm   = w >> 2;      // 0..1 (64-row strip)
    const int wn   = w & 3;       // 0..3 (32-col strip)
    const int bx   = blockIdx.x;  // n tile 0..127
    const int by   = blockIdx.y;  // m tile 0..15
    const int nn_b = by >> 1;     // batch
    const int mcol = (by & 1) * 128;

    const __half* gA = g_A + (size_t)nn_b * K_ * S_ + mcol;
    const __half* gB = g_B + (size_t)bx * BN;

    float acc[4][4][4];
    #pragma unroll
    for (int i = 0; i < 4; ++i)
        #pragma unroll
        for (int j = 0; j < 4; ++j)
            #pragma unroll
            for (int k = 0; k < 4; ++k)
                acc[i][j][k] = 0.0f;

    // PDL: wait until convert's writes are visible
    cudaGridDependencySynchronize();

    // ---- prefetch ALL four K-chunks (stepped groups) ----
    #pragma unroll
    for (int kb = 0; kb < NKB; ++kb) {
        const int kk0 = kb * BK;
        const uint32_t st = sbase + kb * STAGE_BYTES;
        #pragma unroll
        for (int it = 0; it < 2; ++it) {          // A: 512 chunks
            int ch = tid + it * 256;
            int k  = ch >> 4, c = ch & 15;
            cp_async16(st + k * 256 + (TSWZ(k, c) << 4),
                       gA + (size_t)(kk0 + k) * S_ + c * 8);
        }
        #pragma unroll
        for (int it = 0; it < 2; ++it) {          // B: 512 chunks
            int ch = tid + it * 256;
            int k  = ch >> 4, c = ch & 15;
            cp_async16(st + BK * 256 + k * 256 + (TSWZ(k, c) << 4),
                       gB + (size_t)(kk0 + k) * NOUT + c * 8);
        }
        cp_commit();
    }

    // hoisted per-thread ldsm address components (k16=0; +16 rows folds into +4096B)
    const int kkB = (lane & 7) + ((lane >> 3) & 1) * 8;
    const int kkA = (lane & 7) + ((lane >> 4) & 1) * 8;
    uint32_t bOff[2], aOff[4];
    #pragma unroll
    for (int ng = 0; ng < 2; ++ng) {
        int nn = wn * 32 + ng * 16 + ((lane >> 4) & 1) * 8;
        bOff[ng] = (uint32_t)(BK * 256 + kkB * 256 + (TSWZ(kkB, nn >> 3) << 4));
    }
    #pragma unroll
    for (int mt = 0; mt < 4; ++mt) {
        int mm = wm * 64 + mt * 16 + ((lane >> 3) & 1) * 8;
        aOff[mt] = (uint32_t)(kkA * 256 + (TSWZ(kkA, mm >> 3) << 4));
    }

    auto compute = [&](int kb) {
        const uint32_t Ab = sbase + kb * STAGE_BYTES;
        uint32_t br[2][4][2];    // [k16][nt][reg]
        uint32_t ar[2][4][4];    // [k16][mt][reg]
        // phase 1: all B fragment loads (4 ldsm)
        #pragma unroll
        for (int k16 = 0; k16 < 2; ++k16)
            #pragma unroll
            for (int ng = 0; ng < 2; ++ng)
                ldsm4t(br[k16][ng * 2][0], br[k16][ng * 2][1],
                       br[k16][ng * 2 + 1][0], br[k16][ng * 2 + 1][1],
                       Ab + bOff[ng] + k16 * 4096);
        // phase 2: all A fragment loads (8 ldsm)
        #pragma unroll
        for (int k16 = 0; k16 < 2; ++k16)
            #pragma unroll
            for (int mt = 0; mt < 4; ++mt)
                ldsm4t(ar[k16][mt][0], ar[k16][mt][1],
                       ar[k16][mt][2], ar[k16][mt][3],
                       Ab + aOff[mt] + k16 * 4096);
        // phase 3: all 32 mma, operands long since requested
        #pragma unroll
        for (int k16 = 0; k16 < 2; ++k16)
            #pragma unroll
            for (int mt = 0; mt < 4; ++mt)
                #pragma unroll
                for (int nt = 0; nt < 4; ++nt)
                    mma16816(acc[mt][nt],
                             ar[k16][mt][0], ar[k16][mt][1],
                             ar[k16][mt][2], ar[k16][mt][3],
                             br[k16][nt][0], br[k16][nt][1]);
    };

    cp_wait<3>(); __syncthreads(); compute(0);
    cp_wait<2>(); __syncthreads(); compute(1);
    cp_wait<1>(); __syncthreads(); compute(2);
    cp_wait<0>(); __syncthreads(); compute(3);

    // ---- epilogue: direct register -> gmem, coalesced STG.64 ----
    float* obase = out + (size_t)nn_b * 4194304;
    #pragma unroll
    for (int mt = 0; mt < 4; ++mt) {
        #pragma unroll
        for (int nt = 0; nt < 4; ++nt) {
            int col = wn * 32 + nt * 8 + ((lane & 3) << 1);
            int j   = bx * BN + col;
            int p   = j >> 4;
            int q   = (j >> 2) & 3;
            int r   = j & 3;
            int sg0 = mcol + wm * 64 + mt * 16 + (lane >> 2);
            {
                size_t addr = (size_t)p * 4096 + (sg0 >> 4) * 256 + q * 64
                            + (sg0 & 15) * 4 + r;
                *(float2*)(obase + addr) = make_float2(acc[mt][nt][0], acc[mt][nt][1]);
            }
            {
                int sg1 = sg0 + 8;
                size_t addr = (size_t)p * 4096 + (sg1 >> 4) * 256 + q * 64
                            + (sg1 & 15) * 4 + r;
                *(float2*)(obase + addr) = make_float2(acc[mt][nt][2], acc[mt][nt][3]);
            }
        }
    }
}

// ---------------- launch ----------------
extern "C" void kernel_launch(void* const* d_in, const int* in_sizes, int n_in,
                              void* d_out, int out_size) {
    const float* y = (const float*)d_in[0];   // [8][128][256]
    const float* W = (const float*)d_in[1];   // [128][16384]
    float* out = (float*)d_out;

    convert_kernel<<<1152, 256>>>(y, W);

    static bool attr_set = false;
    if (!attr_set) {
        cudaFuncSetAttribute(gemm_fp16_kernel,
                             cudaFuncAttributeMaxDynamicSharedMemorySize, SM_TOTAL);
        attr_set = true;
    }

    cudaLaunchConfig_t cfg = {};
    cfg.gridDim  = dim3(NOUT / BN, M_ / BM);   // (128, 16)
    cfg.blockDim = dim3(256, 1, 1);
    cfg.dynamicSmemBytes = SM_TOTAL;
    cfg.stream = 0;
    cudaLaunchAttribute attrs[1];
    attrs[0].id = cudaLaunchAttributeProgrammaticStreamSerialization;
    attrs[0].val.programmaticStreamSerializationAllowed = 1;
    cfg.attrs = attrs;
    cfg.numAttrs = 1;
    cudaLaunchKernelEx(&cfg, gemm_fp16_kernel, out);
}

// round 17
// speedup vs baseline: 1.1031x; 1.1031x over previous
#include <cuda_runtime.h>
#include <cuda_fp16.h>
#include <cstdint>

// ---------------- problem constants ----------------
#define B_    8
#define K_    128
#define S_    256
#define NOUT  16384
#define M_    2048
#define BM    128
#define BN    128
#define BK    32
#define NKB   4
#define STAGE_BYTES (BK * 256 * 2)             // A[32][256B] + B[32][256B] = 16KB
#define SM_TOTAL (NKB * STAGE_BYTES)           // 64KB, full-K prefetch

// ---------------- scratch: fp16, SAME layout as sources ----------------
__device__ __align__(16) __half g_A[B_ * K_ * S_];     // [n][k][s]   512 KB
__device__ __align__(16) __half g_B[K_ * NOUT];        // [k][j]      4 MB

// ---------------- helpers ----------------
__device__ __forceinline__ uint32_t smem_u32(const void* p) {
    uint32_t a;
    asm("{ .reg .u64 t; cvta.to.shared.u64 t, %1; cvt.u32.u64 %0, t; }" : "=r"(a) : "l"(p));
    return a;
}
__device__ __forceinline__ void cp_async16(uint32_t saddr, const void* gaddr) {
    asm volatile("cp.async.cg.shared.global [%0], [%1], 16;" :: "r"(saddr), "l"(gaddr));
}
__device__ __forceinline__ void cp_commit() {
    asm volatile("cp.async.commit_group;" ::: "memory");
}
template <int N>
__device__ __forceinline__ void cp_wait() {
    asm volatile("cp.async.wait_group %0;" :: "n"(N) : "memory");
}
__device__ __forceinline__ void ldsm4t(uint32_t& r0, uint32_t& r1, uint32_t& r2, uint32_t& r3,
                                       uint32_t addr) {
    asm volatile("ldmatrix.sync.aligned.m8n8.x4.trans.shared.b16 {%0,%1,%2,%3}, [%4];"
                 : "=r"(r0), "=r"(r1), "=r"(r2), "=r"(r3) : "r"(addr));
}
__device__ __forceinline__ void mma16816(float* d, uint32_t a0, uint32_t a1, uint32_t a2,
                                         uint32_t a3, uint32_t b0, uint32_t b1) {
    asm volatile(
        "mma.sync.aligned.m16n8k16.row.col.f32.f16.f16.f32 "
        "{%0,%1,%2,%3}, {%4,%5,%6,%7}, {%8,%9}, {%0,%1,%2,%3};"
        : "+f"(d[0]), "+f"(d[1]), "+f"(d[2]), "+f"(d[3])
        : "r"(a0), "r"(a1), "r"(a2), "r"(a3), "r"(b0), "r"(b1));
}
// streaming store: evict-first in L2 (output is never re-read)
__device__ __forceinline__ void stg_cs_f2(float* p, float x, float y) {
    asm volatile("st.global.cs.v2.f32 [%0], {%1, %2};" :: "l"(p), "f"(x), "f"(y) : "memory");
}

// ---------------- pre-kernel: pure streaming fp32 -> fp16 cast ----------------
__global__ __launch_bounds__(256)
void convert_kernel(const float* __restrict__ y, const float* __restrict__ W) {
    const int bid = blockIdx.x;
    const float* s;
    __half* d;
    if (bid < 1024) {
        size_t u = (size_t)bid * 256 + threadIdx.x;
        s = W + u * 8;  d = g_B + u * 8;
    } else {
        size_t u = (size_t)(bid - 1024) * 256 + threadIdx.x;
        s = y + u * 8;  d = g_A + u * 8;
    }
    float4 v0 = ((const float4*)s)[0];
    float4 v1 = ((const float4*)s)[1];
    __half2 h0 = __floats2half2_rn(v0.x, v0.y);
    __half2 h1 = __floats2half2_rn(v0.z, v0.w);
    __half2 h2 = __floats2half2_rn(v1.x, v1.y);
    __half2 h3 = __floats2half2_rn(v1.z, v1.w);
    uint4 o;
    o.x = *(uint32_t*)&h0; o.y = *(uint32_t*)&h1;
    o.z = *(uint32_t*)&h2; o.w = *(uint32_t*)&h3;
    *(uint4*)d = o;
    cudaTriggerProgrammaticLaunchCompletion();
}

// smem tile layout: [32 k-rows][256B], 16B chunk swizzle  c' = c ^ (k & 7)
#define TSWZ(k, c) ((c) ^ ((k) & 7))

// ---------------- main GEMM kernel (R15 structure + streaming stores) ----------------
__global__ __launch_bounds__(256, 2)
void gemm_fp16_kernel(float* __restrict__ out) {
    extern __shared__ char smem[];
    const uint32_t sbase = smem_u32(smem);
    const int tid  = threadIdx.x;
    const int lane = tid & 31;
    const int w    = tid >> 5;
    const int wm   = w >> 2;      // 0..1 (64-row strip)
    const int wn   = w & 3;       // 0..3 (32-col strip)
    const int bx   = blockIdx.x;  // n tile 0..127
    const int by   = blockIdx.y;  // m tile 0..15
    const int nn_b = by >> 1;     // batch
    const int mcol = (by & 1) * 128;

    const __half* gA = g_A + (size_t)nn_b * K_ * S_ + mcol;
    const __half* gB = g_B + (size_t)bx * BN;

    float acc[4][4][4];
    #pragma unroll
    for (int i = 0; i < 4; ++i)
        #pragma unroll
        for (int j = 0; j < 4; ++j)
            #pragma unroll
            for (int k = 0; k < 4; ++k)
                acc[i][j][k] = 0.0f;

    // PDL: wait until convert's writes are visible
    cudaGridDependencySynchronize();

    // ---- prefetch ALL four K-chunks (stepped groups) ----
    #pragma unroll
    for (int kb = 0; kb < NKB; ++kb) {
        const int kk0 = kb * BK;
        const uint32_t st = sbase + kb * STAGE_BYTES;
        #pragma unroll
        for (int it = 0; it < 2; ++it) {          // A: 512 chunks
            int ch = tid + it * 256;
            int k  = ch >> 4, c = ch & 15;
            cp_async16(st + k * 256 + (TSWZ(k, c) << 4),
                       gA + (size_t)(kk0 + k) * S_ + c * 8);
        }
        #pragma unroll
        for (int it = 0; it < 2; ++it) {          // B: 512 chunks
            int ch = tid + it * 256;
            int k  = ch >> 4, c = ch & 15;
            cp_async16(st + BK * 256 + k * 256 + (TSWZ(k, c) << 4),
                       gB + (size_t)(kk0 + k) * NOUT + c * 8);
        }
        cp_commit();
    }

    auto compute = [&](int kb) {
        const uint32_t Ab = sbase + kb * STAGE_BYTES;
        const uint32_t Bb = Ab + BK * 256;
        #pragma unroll
        for (int k16 = 0; k16 < 2; ++k16) {
            uint32_t br[4][2];
            #pragma unroll
            for (int ng = 0; ng < 2; ++ng) {
                int kk = k16 * 16 + (lane & 7) + ((lane >> 3) & 1) * 8;
                int nn = wn * 32 + ng * 16 + ((lane >> 4) & 1) * 8;
                uint32_t addr = Bb + kk * 256 + (TSWZ(kk, nn >> 3) << 4);
                uint32_t b0, b1, b2, b3;
                ldsm4t(b0, b1, b2, b3, addr);
                br[ng * 2][0] = b0;     br[ng * 2][1] = b1;
                br[ng * 2 + 1][0] = b2; br[ng * 2 + 1][1] = b3;
            }
            #pragma unroll
            for (int mt = 0; mt < 4; ++mt) {
                int kk = k16 * 16 + (lane & 7) + ((lane >> 4) & 1) * 8;
                int mm = wm * 64 + mt * 16 + ((lane >> 3) & 1) * 8;
                uint32_t addr = Ab + kk * 256 + (TSWZ(kk, mm >> 3) << 4);
                uint32_t a0, a1, a2, a3;
                ldsm4t(a0, a1, a2, a3, addr);
                #pragma unroll
                for (int nt = 0; nt < 4; ++nt)
                    mma16816(acc[mt][nt], a0, a1, a2, a3, br[nt][0], br[nt][1]);
            }
        }
    };

    cp_wait<3>(); __syncthreads(); compute(0);
    cp_wait<2>(); __syncthreads(); compute(1);
    cp_wait<1>(); __syncthreads(); compute(2);
    cp_wait<0>(); __syncthreads(); compute(3);

    // ---- epilogue: direct register -> gmem, coalesced STREAMING STG.64 ----
    float* obase = out + (size_t)nn_b * 4194304;
    #pragma unroll
    for (int mt = 0; mt < 4; ++mt) {
        #pragma unroll
        for (int nt = 0; nt < 4; ++nt) {
            int col = wn * 32 + nt * 8 + ((lane & 3) << 1);
            int j   = bx * BN + col;
            int p   = j >> 4;
            int q   = (j >> 2) & 3;
            int r   = j & 3;
            int sg0 = mcol + wm * 64 + mt * 16 + (lane >> 2);
            {
                size_t addr = (size_t)p * 4096 + (sg0 >> 4) * 256 + q * 64
                            + (sg0 & 15) * 4 + r;
                stg_cs_f2(obase + addr, acc[mt][nt][0], acc[mt][nt][1]);
            }
            {
                int sg1 = sg0 + 8;
                size_t addr = (size_t)p * 4096 + (sg1 >> 4) * 256 + q * 64
                            + (sg1 & 15) * 4 + r;
                stg_cs_f2(obase + addr, acc[mt][nt][2], acc[mt][nt][3]);
            }
        }
    }
}

// ---------------- launch ----------------
extern "C" void kernel_launch(void* const* d_in, const int* in_sizes, int n_in,
                              void* d_out, int out_size) {
    const float* y = (const float*)d_in[0];   // [8][128][256]
    const float* W = (const float*)d_in[1];   // [128][16384]
    float* out = (float*)d_out;

    convert_kernel<<<1152, 256>>>(y, W);

    static bool attr_set = false;
    if (!attr_set) {
        cudaFuncSetAttribute(gemm_fp16_kernel,
                             cudaFuncAttributeMaxDynamicSharedMemorySize, SM_TOTAL);
        attr_set = true;
    }

    cudaLaunchConfig_t cfg = {};
    cfg.gridDim  = dim3(NOUT / BN, M_ / BM);   // (128, 16)
    cfg.blockDim = dim3(256, 1, 1);
    cfg.dynamicSmemBytes = SM_TOTAL;
    cfg.stream = 0;
    cudaLaunchAttribute attrs[1];
    attrs[0].id = cudaLaunchAttributeProgrammaticStreamSerialization;
    attrs[0].val.programmaticStreamSerializationAllowed = 1;
    cfg.attrs = attrs;
    cfg.numAttrs = 1;
    cudaLaunchKernelEx(&cfg, gemm_fp16_kernel, out);
}